// round 1
// baseline (speedup 1.0000x reference)
#include <cuda_runtime.h>
#include <math_constants.h>

#define C       384
#define DH      64
#define CTXC    128
#define BT      10
#define TFRAMES 5
#define NSTG    4
#define QSCALE  0.125f

// Total pixels per (stage) summed over b: 10*hw
// hw:        6400, 1600, 400, 100
// pix offs (10*hw cumulative): 0, 64000, 80000, 84000, 85000
#define NPIX_TOTAL 85000
#define VOUT_TOTAL 32640000   // 10*384*8500

__constant__ int   c_hw[NSTG]      = {6400, 1600, 400, 100};
__constant__ int   c_pixoff[NSTG]  = {0, 64000, 80000, 84000};
__constant__ int   c_voutoff[NSTG] = {0, 24576000, 30720000, 32256000};

__device__ float g_wq  [NSTG * BT * C];
__device__ float g_y   [NSTG * BT * C];
__device__ float g_xbar[NSTG * BT * C];
__device__ float g_sim [NPIX_TOTAL];

// ---------------------------------------------------------------------------
// K1: per-(stage, b) small algebra.
//   a    = Wp @ audio + bp                       [C]
//   cqk  = Wcqk @ (a + pe[t])                    [DH]
//   cv   = Wcv  @ a                              [DH]
//   y    = Wo @ cv + bo      (vout broadcast)    [C]
//   wq   = SCALE * (cqk @ Wqk)                   [C]
// ---------------------------------------------------------------------------
__global__ void k_setup(const float* __restrict__ a0, const float* __restrict__ a1,
                        const float* __restrict__ a2, const float* __restrict__ a3,
                        const float* __restrict__ ctx_proj_w, const float* __restrict__ ctx_proj_b,
                        const float* __restrict__ pos_emb,
                        const float* __restrict__ qk_w, const float* __restrict__ ctx_qk_w,
                        const float* __restrict__ ctx_v_w,
                        const float* __restrict__ out_w, const float* __restrict__ out_b)
{
    int s = blockIdx.x / BT;
    int b = blockIdx.x % BT;
    const float* audio = (s == 0 ? a0 : s == 1 ? a1 : s == 2 ? a2 : a3) + b * CTXC;

    __shared__ float sh_a[C];
    __shared__ float sh_cqk[DH];
    __shared__ float sh_cv[DH];

    int c = threadIdx.x;

    // a[c]
    {
        float acc = ctx_proj_b[s * C + c];
        const float* wp = ctx_proj_w + ((size_t)s * C + c) * CTXC;
        #pragma unroll 8
        for (int k = 0; k < CTXC; k++) acc += wp[k] * audio[k];
        sh_a[c] = acc;
    }
    __syncthreads();

    if (c < DH) {
        const float* pe   = pos_emb  + ((size_t)s * TFRAMES + (b % TFRAMES)) * C;
        const float* wcqk = ctx_qk_w + ((size_t)s * DH + c) * C;
        const float* wcv  = ctx_v_w  + ((size_t)s * DH + c) * C;
        float s1 = 0.f, s2 = 0.f;
        #pragma unroll 4
        for (int j = 0; j < C; j++) {
            float av = sh_a[j];
            s1 += wcqk[j] * (av + pe[j]);
            s2 += wcv[j] * av;
        }
        sh_cqk[c] = s1;
        sh_cv[c]  = s2;
    }
    __syncthreads();

    // y[c] = Wo @ cv + bo
    {
        float yv = out_b[s * C + c];
        const float* wo = out_w + ((size_t)s * C + c) * DH;
        #pragma unroll 8
        for (int d = 0; d < DH; d++) yv += wo[d] * sh_cv[d];
        g_y[(s * BT + b) * C + c] = yv;
    }
    // wq[c] = SCALE * sum_d cqk[d] * Wqk[d,c]
    {
        float wv = 0.f;
        const float* wqk = qk_w + (size_t)s * DH * C + c;   // stride C over d
        #pragma unroll 8
        for (int d = 0; d < DH; d++) wv += sh_cqk[d] * wqk[(size_t)d * C];
        g_wq[(s * BT + b) * C + c] = wv * QSCALE;
    }
}

// ---------------------------------------------------------------------------
// K2: one thread per pixel (flattened over stages).
//   sim[g]     = sum_c (x[b,c,i] + pos[b,c,i]) * wq[s,b,c]
//   vout[...]  = y[s,b,c]   (broadcast write, fused into the same c-loop)
// ---------------------------------------------------------------------------
__global__ void k_sim_vout(const float* __restrict__ x0, const float* __restrict__ x1,
                           const float* __restrict__ x2, const float* __restrict__ x3,
                           const float* __restrict__ p0, const float* __restrict__ p1,
                           const float* __restrict__ p2, const float* __restrict__ p3,
                           float* __restrict__ out)
{
    int g = blockIdx.x * blockDim.x + threadIdx.x;
    if (g >= NPIX_TOTAL) return;

    int s;
    if      (g < 64000) s = 0;
    else if (g < 80000) s = 1;
    else if (g < 84000) s = 2;
    else                s = 3;

    const int hw    = c_hw[s];
    const int local = g - c_pixoff[s];
    const int b     = local / hw;
    const int i     = local - b * hw;

    const float* x = (s == 0 ? x0 : s == 1 ? x1 : s == 2 ? x2 : x3);
    const float* p = (s == 0 ? p0 : s == 1 ? p1 : s == 2 ? p2 : p3);

    const float* xb = x + ((size_t)b * C) * hw + i;
    const float* pb = p + ((size_t)b * C) * hw + i;
    const float* wq = g_wq + (s * BT + b) * C;
    const float* yv = g_y  + (s * BT + b) * C;
    float* vout = out + c_voutoff[s] + ((size_t)b * C) * hw + i;

    float acc = 0.f;
    #pragma unroll 8
    for (int c = 0; c < C; c++) {
        float xv = xb[(size_t)c * hw];
        float pv = pb[(size_t)c * hw];
        acc = fmaf(xv + pv, wq[c], acc);
        vout[(size_t)c * hw] = yv[c];
    }
    g_sim[g] = acc;
}

// ---------------------------------------------------------------------------
// K3: xbar[s,b,c] = sum_i softmax_i(sim[s,b,:]) * x[b,c,i]
// One block per (stage, b, channel-group of 16). Block recomputes softmax
// weights p[] into smem (cheap: <= 25.6KB of sim), then 8 warps x 2 channels.
// ---------------------------------------------------------------------------
#define CG        16
#define NGROUPS   (C / CG)          // 24
#define XBAR_THREADS 256

__global__ __launch_bounds__(XBAR_THREADS)
void k_xbar(const float* __restrict__ x0, const float* __restrict__ x1,
            const float* __restrict__ x2, const float* __restrict__ x3)
{
    int blk = blockIdx.x;
    int grp = blk % NGROUPS;
    int sb  = blk / NGROUPS;
    int s   = sb / BT;
    int b   = sb % BT;
    const int hw = c_hw[s];

    const float* sim = g_sim + c_pixoff[s] + b * hw;

    __shared__ float sh_p[6400];
    __shared__ float sh_red[8];
    __shared__ float sh_bc[2];

    const int tid  = threadIdx.x;
    const int lane = tid & 31;
    const int warp = tid >> 5;

    // --- max reduce ---
    float m = -CUDART_INF_F;
    for (int i = tid; i < hw; i += XBAR_THREADS) m = fmaxf(m, sim[i]);
    #pragma unroll
    for (int o = 16; o > 0; o >>= 1) m = fmaxf(m, __shfl_down_sync(0xffffffffu, m, o));
    if (lane == 0) sh_red[warp] = m;
    __syncthreads();
    if (tid < 8) {
        float v = sh_red[tid];
        #pragma unroll
        for (int o = 4; o > 0; o >>= 1) v = fmaxf(v, __shfl_down_sync(0xffu, v, o));
        if (tid == 0) sh_bc[0] = v;
    }
    __syncthreads();
    m = sh_bc[0];

    // --- exp + sum reduce, store p ---
    float ssum = 0.f;
    for (int i = tid; i < hw; i += XBAR_THREADS) {
        float e = expf(sim[i] - m);
        sh_p[i] = e;
        ssum += e;
    }
    #pragma unroll
    for (int o = 16; o > 0; o >>= 1) ssum += __shfl_down_sync(0xffffffffu, ssum, o);
    if (lane == 0) sh_red[warp] = ssum;
    __syncthreads();
    if (tid < 8) {
        float v = sh_red[tid];
        #pragma unroll
        for (int o = 4; o > 0; o >>= 1) v += __shfl_down_sync(0xffu, v, o);
        if (tid == 0) sh_bc[1] = 1.f / v;
    }
    __syncthreads();
    const float rinv = sh_bc[1];

    const float* x = (s == 0 ? x0 : s == 1 ? x1 : s == 2 ? x2 : x3);

    // 8 warps * 2 channels each = 16 channels
    #pragma unroll
    for (int cc = 0; cc < 2; cc++) {
        int c = grp * CG + warp * 2 + cc;
        const float* xc = x + ((size_t)b * C + c) * hw;
        float acc = 0.f;
        for (int i = lane; i < hw; i += 32) acc = fmaf(sh_p[i], xc[i], acc);
        #pragma unroll
        for (int o = 16; o > 0; o >>= 1) acc += __shfl_down_sync(0xffffffffu, acc, o);
        if (lane == 0) g_xbar[(s * BT + b) * C + c] = acc * rinv;
    }
}

// ---------------------------------------------------------------------------
// K4: aout[s,b,c] = ctx_out_b + Wco @ (Wv @ xbar)
// ---------------------------------------------------------------------------
__global__ void k_aout(const float* __restrict__ v_w,
                       const float* __restrict__ ctx_out_w,
                       const float* __restrict__ ctx_out_b,
                       float* __restrict__ out)
{
    int s = blockIdx.x / BT;
    int b = blockIdx.x % BT;
    __shared__ float sh_xb[C];
    __shared__ float sh_t[DH];

    int c = threadIdx.x;
    sh_xb[c] = g_xbar[(s * BT + b) * C + c];
    __syncthreads();

    if (c < DH) {
        const float* wv = v_w + ((size_t)s * DH + c) * C;
        float acc = 0.f;
        #pragma unroll 4
        for (int j = 0; j < C; j++) acc += wv[j] * sh_xb[j];
        sh_t[c] = acc;
    }
    __syncthreads();

    float acc = ctx_out_b[s * C + c];
    const float* wco = ctx_out_w + ((size_t)s * C + c) * DH;
    #pragma unroll 8
    for (int d = 0; d < DH; d++) acc += wco[d] * sh_t[d];
    out[VOUT_TOTAL + (s * BT + b) * C + c] = acc;
}

// ---------------------------------------------------------------------------
extern "C" void kernel_launch(void* const* d_in, const int* in_sizes, int n_in,
                              void* d_out, int out_size)
{
    const float *fm[NSTG], *ps[NSTG], *au[NSTG];
    // Disambiguate input ordering:
    //   dict order:      fmap0,pos0,audio0, fmap1,pos1,audio1, ... (in_sizes[1]==in_sizes[0])
    //   signature order: fmap0..3, audio0..3, pos0..3
    bool dict_order = (in_sizes[1] == in_sizes[0]);
    if (dict_order) {
        for (int s = 0; s < NSTG; s++) {
            fm[s] = (const float*)d_in[3 * s + 0];
            ps[s] = (const float*)d_in[3 * s + 1];
            au[s] = (const float*)d_in[3 * s + 2];
        }
    } else {
        for (int s = 0; s < NSTG; s++) {
            fm[s] = (const float*)d_in[s];
            au[s] = (const float*)d_in[4 + s];
            ps[s] = (const float*)d_in[8 + s];
        }
    }
    const float* ctx_proj_w = (const float*)d_in[12];
    const float* ctx_proj_b = (const float*)d_in[13];
    const float* pos_emb    = (const float*)d_in[14];
    const float* qk_w       = (const float*)d_in[15];
    const float* ctx_qk_w   = (const float*)d_in[16];
    const float* v_w        = (const float*)d_in[17];
    const float* ctx_v_w    = (const float*)d_in[18];
    const float* out_w      = (const float*)d_in[19];
    const float* out_b      = (const float*)d_in[20];
    const float* ctx_out_w  = (const float*)d_in[21];
    const float* ctx_out_b  = (const float*)d_in[22];

    float* out = (float*)d_out;

    k_setup<<<NSTG * BT, C>>>(au[0], au[1], au[2], au[3],
                              ctx_proj_w, ctx_proj_b, pos_emb,
                              qk_w, ctx_qk_w, ctx_v_w, out_w, out_b);

    k_sim_vout<<<(NPIX_TOTAL + 255) / 256, 256>>>(fm[0], fm[1], fm[2], fm[3],
                                                  ps[0], ps[1], ps[2], ps[3], out);

    k_xbar<<<NSTG * BT * NGROUPS, XBAR_THREADS>>>(fm[0], fm[1], fm[2], fm[3]);

    k_aout<<<NSTG * BT, C>>>(v_w, ctx_out_w, ctx_out_b, out);
}

// round 2
// speedup vs baseline: 1.0186x; 1.0186x over previous
#include <cuda_runtime.h>
#include <math_constants.h>

#define C       384
#define DH      64
#define CTXC    128
#define BT      10
#define TFRAMES 5
#define NSTG    4
#define QSCALE  0.125f

// Total pixels per (stage) summed over b: 10*hw
// hw:        6400, 1600, 400, 100
// pix offs (10*hw cumulative): 0, 64000, 80000, 84000, 85000
#define NPIX_TOTAL 85000
#define VOUT_TOTAL 32640000   // 10*384*8500

__constant__ int   c_hw[NSTG]      = {6400, 1600, 400, 100};
__constant__ int   c_pixoff[NSTG]  = {0, 64000, 80000, 84000};
__constant__ int   c_voutoff[NSTG] = {0, 24576000, 30720000, 32256000};

__device__ float g_wq  [NSTG * BT * C];
__device__ float g_y   [NSTG * BT * C];
__device__ float g_xbar[NSTG * BT * C];
__device__ float g_sim [NPIX_TOTAL];

// ---------------------------------------------------------------------------
// K1: per-(stage, b) small algebra.
//   a    = Wp @ audio + bp                       [C]
//   cqk  = Wcqk @ (a + pe[t])                    [DH]
//   cv   = Wcv  @ a                              [DH]
//   y    = Wo @ cv + bo      (vout broadcast)    [C]
//   wq   = SCALE * (cqk @ Wqk)                   [C]
// ---------------------------------------------------------------------------
__global__ void k_setup(const float* __restrict__ a0, const float* __restrict__ a1,
                        const float* __restrict__ a2, const float* __restrict__ a3,
                        const float* __restrict__ ctx_proj_w, const float* __restrict__ ctx_proj_b,
                        const float* __restrict__ pos_emb,
                        const float* __restrict__ qk_w, const float* __restrict__ ctx_qk_w,
                        const float* __restrict__ ctx_v_w,
                        const float* __restrict__ out_w, const float* __restrict__ out_b)
{
    int s = blockIdx.x / BT;
    int b = blockIdx.x % BT;
    const float* audio = (s == 0 ? a0 : s == 1 ? a1 : s == 2 ? a2 : a3) + b * CTXC;

    __shared__ float sh_a[C];
    __shared__ float sh_cqk[DH];
    __shared__ float sh_cv[DH];

    int c = threadIdx.x;

    // a[c]
    {
        float acc = ctx_proj_b[s * C + c];
        const float* wp = ctx_proj_w + ((size_t)s * C + c) * CTXC;
        #pragma unroll 8
        for (int k = 0; k < CTXC; k++) acc += wp[k] * audio[k];
        sh_a[c] = acc;
    }
    __syncthreads();

    if (c < DH) {
        const float* pe   = pos_emb  + ((size_t)s * TFRAMES + (b % TFRAMES)) * C;
        const float* wcqk = ctx_qk_w + ((size_t)s * DH + c) * C;
        const float* wcv  = ctx_v_w  + ((size_t)s * DH + c) * C;
        float s1 = 0.f, s2 = 0.f;
        #pragma unroll 4
        for (int j = 0; j < C; j++) {
            float av = sh_a[j];
            s1 += wcqk[j] * (av + pe[j]);
            s2 += wcv[j] * av;
        }
        sh_cqk[c] = s1;
        sh_cv[c]  = s2;
    }
    __syncthreads();

    // y[c] = Wo @ cv + bo
    {
        float yv = out_b[s * C + c];
        const float* wo = out_w + ((size_t)s * C + c) * DH;
        #pragma unroll 8
        for (int d = 0; d < DH; d++) yv += wo[d] * sh_cv[d];
        g_y[(s * BT + b) * C + c] = yv;
    }
    // wq[c] = SCALE * sum_d cqk[d] * Wqk[d,c]
    {
        float wv = 0.f;
        const float* wqk = qk_w + (size_t)s * DH * C + c;   // stride C over d
        #pragma unroll 8
        for (int d = 0; d < DH; d++) wv += sh_cqk[d] * wqk[(size_t)d * C];
        g_wq[(s * BT + b) * C + c] = wv * QSCALE;
    }
}

// ---------------------------------------------------------------------------
// K2: one thread per pixel (flattened over stages).
//   sim[g]     = sum_c (x[b,c,i] + pos[b,c,i]) * wq[s,b,c]
//   vout[...]  = y[s,b,c]   (broadcast write, fused into the same c-loop)
// ---------------------------------------------------------------------------
__global__ void k_sim_vout(const float* __restrict__ x0, const float* __restrict__ x1,
                           const float* __restrict__ x2, const float* __restrict__ x3,
                           const float* __restrict__ p0, const float* __restrict__ p1,
                           const float* __restrict__ p2, const float* __restrict__ p3,
                           float* __restrict__ out)
{
    int g = blockIdx.x * blockDim.x + threadIdx.x;
    if (g >= NPIX_TOTAL) return;

    int s;
    if      (g < 64000) s = 0;
    else if (g < 80000) s = 1;
    else if (g < 84000) s = 2;
    else                s = 3;

    const int hw    = c_hw[s];
    const int local = g - c_pixoff[s];
    const int b     = local / hw;
    const int i     = local - b * hw;

    const float* x = (s == 0 ? x0 : s == 1 ? x1 : s == 2 ? x2 : x3);
    const float* p = (s == 0 ? p0 : s == 1 ? p1 : s == 2 ? p2 : p3);

    const float* xb = x + ((size_t)b * C) * hw + i;
    const float* pb = p + ((size_t)b * C) * hw + i;
    const float* wq = g_wq + (s * BT + b) * C;
    const float* yv = g_y  + (s * BT + b) * C;
    float* vout = out + c_voutoff[s] + ((size_t)b * C) * hw + i;

    float acc = 0.f;
    #pragma unroll 8
    for (int c = 0; c < C; c++) {
        float xv = xb[(size_t)c * hw];
        float pv = pb[(size_t)c * hw];
        acc = fmaf(xv + pv, wq[c], acc);
        vout[(size_t)c * hw] = yv[c];
    }
    g_sim[g] = acc;
}

// ---------------------------------------------------------------------------
// K3: xbar[s,b,c] = sum_i softmax_i(sim[s,b,:]) * x[b,c,i]
// One block per (stage, b, channel-group of 16). Block recomputes softmax
// weights p[] into smem (cheap: <= 25.6KB of sim), then 8 warps x 2 channels.
// ---------------------------------------------------------------------------
#define CG        16
#define NGROUPS   (C / CG)          // 24
#define XBAR_THREADS 256

__global__ __launch_bounds__(XBAR_THREADS)
void k_xbar(const float* __restrict__ x0, const float* __restrict__ x1,
            const float* __restrict__ x2, const float* __restrict__ x3)
{
    int blk = blockIdx.x;
    int grp = blk % NGROUPS;
    int sb  = blk / NGROUPS;
    int s   = sb / BT;
    int b   = sb % BT;
    const int hw = c_hw[s];

    const float* sim = g_sim + c_pixoff[s] + b * hw;

    __shared__ float sh_p[6400];
    __shared__ float sh_red[8];
    __shared__ float sh_bc[2];

    const int tid  = threadIdx.x;
    const int lane = tid & 31;
    const int warp = tid >> 5;

    // --- max reduce ---
    float m = -CUDART_INF_F;
    for (int i = tid; i < hw; i += XBAR_THREADS) m = fmaxf(m, sim[i]);
    #pragma unroll
    for (int o = 16; o > 0; o >>= 1) m = fmaxf(m, __shfl_down_sync(0xffffffffu, m, o));
    if (lane == 0) sh_red[warp] = m;
    __syncthreads();
    if (tid < 8) {
        float v = sh_red[tid];
        #pragma unroll
        for (int o = 4; o > 0; o >>= 1) v = fmaxf(v, __shfl_down_sync(0xffu, v, o));
        if (tid == 0) sh_bc[0] = v;
    }
    __syncthreads();
    m = sh_bc[0];

    // --- exp + sum reduce, store p ---
    float ssum = 0.f;
    for (int i = tid; i < hw; i += XBAR_THREADS) {
        float e = expf(sim[i] - m);
        sh_p[i] = e;
        ssum += e;
    }
    #pragma unroll
    for (int o = 16; o > 0; o >>= 1) ssum += __shfl_down_sync(0xffffffffu, ssum, o);
    if (lane == 0) sh_red[warp] = ssum;
    __syncthreads();
    if (tid < 8) {
        float v = sh_red[tid];
        #pragma unroll
        for (int o = 4; o > 0; o >>= 1) v += __shfl_down_sync(0xffu, v, o);
        if (tid == 0) sh_bc[1] = 1.f / v;
    }
    __syncthreads();
    const float rinv = sh_bc[1];

    const float* x = (s == 0 ? x0 : s == 1 ? x1 : s == 2 ? x2 : x3);

    // 8 warps * 2 channels each = 16 channels
    #pragma unroll
    for (int cc = 0; cc < 2; cc++) {
        int c = grp * CG + warp * 2 + cc;
        const float* xc = x + ((size_t)b * C + c) * hw;
        float acc = 0.f;
        for (int i = lane; i < hw; i += 32) acc = fmaf(sh_p[i], xc[i], acc);
        #pragma unroll
        for (int o = 16; o > 0; o >>= 1) acc += __shfl_down_sync(0xffffffffu, acc, o);
        if (lane == 0) g_xbar[(s * BT + b) * C + c] = acc * rinv;
    }
}

// ---------------------------------------------------------------------------
// K4: aout[s,b,c] = ctx_out_b + Wco @ (Wv @ xbar)
// ---------------------------------------------------------------------------
__global__ void k_aout(const float* __restrict__ v_w,
                       const float* __restrict__ ctx_out_w,
                       const float* __restrict__ ctx_out_b,
                       float* __restrict__ out)
{
    int s = blockIdx.x / BT;
    int b = blockIdx.x % BT;
    __shared__ float sh_xb[C];
    __shared__ float sh_t[DH];

    int c = threadIdx.x;
    sh_xb[c] = g_xbar[(s * BT + b) * C + c];
    __syncthreads();

    if (c < DH) {
        const float* wv = v_w + ((size_t)s * DH + c) * C;
        float acc = 0.f;
        #pragma unroll 4
        for (int j = 0; j < C; j++) acc += wv[j] * sh_xb[j];
        sh_t[c] = acc;
    }
    __syncthreads();

    float acc = ctx_out_b[s * C + c];
    const float* wco = ctx_out_w + ((size_t)s * C + c) * DH;
    #pragma unroll 8
    for (int d = 0; d < DH; d++) acc += wco[d] * sh_t[d];
    out[VOUT_TOTAL + (s * BT + b) * C + c] = acc;
}

// ---------------------------------------------------------------------------
extern "C" void kernel_launch(void* const* d_in, const int* in_sizes, int n_in,
                              void* d_out, int out_size)
{
    const float *fm[NSTG], *ps[NSTG], *au[NSTG];
    // Disambiguate input ordering:
    //   dict order:      fmap0,pos0,audio0, fmap1,pos1,audio1, ... (in_sizes[1]==in_sizes[0])
    //   signature order: fmap0..3, audio0..3, pos0..3
    bool dict_order = (in_sizes[1] == in_sizes[0]);
    if (dict_order) {
        for (int s = 0; s < NSTG; s++) {
            fm[s] = (const float*)d_in[3 * s + 0];
            ps[s] = (const float*)d_in[3 * s + 1];
            au[s] = (const float*)d_in[3 * s + 2];
        }
    } else {
        for (int s = 0; s < NSTG; s++) {
            fm[s] = (const float*)d_in[s];
            au[s] = (const float*)d_in[4 + s];
            ps[s] = (const float*)d_in[8 + s];
        }
    }
    const float* ctx_proj_w = (const float*)d_in[12];
    const float* ctx_proj_b = (const float*)d_in[13];
    const float* pos_emb    = (const float*)d_in[14];
    const float* qk_w       = (const float*)d_in[15];
    const float* ctx_qk_w   = (const float*)d_in[16];
    const float* v_w        = (const float*)d_in[17];
    const float* ctx_v_w    = (const float*)d_in[18];
    const float* out_w      = (const float*)d_in[19];
    const float* out_b      = (const float*)d_in[20];
    const float* ctx_out_w  = (const float*)d_in[21];
    const float* ctx_out_b  = (const float*)d_in[22];

    float* out = (float*)d_out;

    k_setup<<<NSTG * BT, C>>>(au[0], au[1], au[2], au[3],
                              ctx_proj_w, ctx_proj_b, pos_emb,
                              qk_w, ctx_qk_w, ctx_v_w, out_w, out_b);

    k_sim_vout<<<(NPIX_TOTAL + 255) / 256, 256>>>(fm[0], fm[1], fm[2], fm[3],
                                                  ps[0], ps[1], ps[2], ps[3], out);

    k_xbar<<<NSTG * BT * NGROUPS, XBAR_THREADS>>>(fm[0], fm[1], fm[2], fm[3]);

    k_aout<<<NSTG * BT, C>>>(v_w, ctx_out_w, ctx_out_b, out);
}